// round 15
// baseline (speedup 1.0000x reference)
#include <cuda_runtime.h>
#include <cstddef>
#include <cstdint>

// ChebychevTransform: x[8,256,256,8] f32 -> out[8,256,256,128] f32
// out[b,h,w, c*16 + p*4 + k] = sum_{i,j} T[p,j]*T[k,i]*x[b,h+i-1,w+j-1,c]
// (zero pad: 1 before / 2 after, TF SAME n=4)
// T = [[1/6,1/3,1/3,1/6],[1/3,1/3,-1/3,-1/3],[1/3,-1/3,-1/3,1/3],[1/3,-2/3,2/3,-1/3]]
//
// Block = 256 thr = (b, 32-col w-tile, 32-row h-group), 4 strips of 8 rows.
// Staging: cp.async 4B global->smem transpose into [t][c][wcol] (TPAD=36,
//          conflict-free), src-size=0 zero-fills the w-halo. No registers, no STS.
// Pipeline: wait+sync for strip s, issue strip s+1's cp.asyncs (overlap with
//          consume), consume, trailing sync guards buffer reuse.
// Consume: warp = 4 adjacent pixel columns; lane=(p=lane>>3,c=lane&7); per row
//          2 broadcast LDS.128 -> 4 sliding 4-tap dots with T[p,:]; vertical
//          register ring; dense .cs STG.128 at channel offset c*16+p*4.

#define HH 256
#define WW 256
#define CC 8
#define ROWF (WW * CC)
#define SS 8
#define NS 4
#define NT 11
#define TCOLS 35
#define TPAD 36
#define TSTRIDE (CC * TPAD)      // 288 floats per staged row
#define NELEM (NT * TCOLS * CC)  // 3080
#define NK 13                    // ceil(3080/256)

__device__ __forceinline__ void cp_async4(uint32_t dst, const float* src, bool valid) {
    int sz = valid ? 4 : 0;
    asm volatile("cp.async.ca.shared.global [%0], [%1], 4, %2;\n"
                 :: "r"(dst), "l"(src), "r"(sz));
}
#define CP_COMMIT() asm volatile("cp.async.commit_group;\n" ::: "memory")
#define CP_WAIT0()  asm volatile("cp.async.wait_group 0;\n" ::: "memory")

__device__ __forceinline__ void cheb4(float x0, float x1, float x2, float x3,
                                      float& y0, float& y1, float& y2, float& y3) {
    const float K3 = 1.0f / 3.0f;
    const float K6 = 1.0f / 6.0f;
    float s0 = x0 + x3, s1 = x1 + x2;
    float d0 = x0 - x3, d1 = x1 - x2;
    y0 = fmaf(s1, K3, s0 * K6);
    y1 = (d0 + d1) * K3;
    y2 = (s0 - s1) * K3;
    y3 = fmaf(d1, -2.0f, d0) * K3;
}

__global__ __launch_bounds__(256)
void cheb_kernel(const float* __restrict__ x, float* __restrict__ out) {
    __shared__ __align__(16) float tile[2][NT * TSTRIDE];   // 2 x 12672 B

    int bx = blockIdx.x;
    int wt = bx & 7;             // 8 w-tiles of 32
    int hg = (bx >> 3) & 7;      // 8 h-groups of 32 rows
    int b  = bx >> 6;
    int w0 = wt * 32;
    int hbase = hg * (SS * NS);

    int tid = threadIdx.x;
    const float* src = x + (size_t)b * HH * ROWF;

    uint32_t smem0 = (uint32_t)__cvta_generic_to_shared(&tile[0][0]);
    uint32_t smem1 = (uint32_t)__cvta_generic_to_shared(&tile[1][0]);

    // ---- cp.async staging of one strip's halo tile (13 x 4B per thread) ----
    auto stage = [&](int h0, uint32_t sb) {
        #pragma unroll
        for (int k = 0; k < NK; k++) {
            int e = tid + k * 256;
            if (e < NELEM) {
                int c    = e & 7;
                int tw   = e >> 3;
                int t    = tw / TCOLS;           // mul-shift, cheap
                int wcol = tw - t * TCOLS;
                int r  = min(max(h0 - 1 + t, 0), HH - 1);
                int wc = w0 - 1 + wcol;
                bool v = (wc >= 0) && (wc < WW);
                const float* g = src + (size_t)r * ROWF + (v ? wc : 0) * CC + c;
                cp_async4(sb + 4u * (t * TSTRIDE + c * TPAD + wcol), g, v);
            }
        }
        CP_COMMIT();
    };

    // ---- consume lane mapping ----
    int lane = tid & 31;
    int wid  = tid >> 5;
    int p  = lane >> 3;
    int c  = lane & 7;
    int wl = wid * 4;

    const float K3 = 1.0f / 3.0f, K6 = 1.0f / 6.0f, K23 = 2.0f / 3.0f;
    float t0c = (p == 0) ? K6 : K3;
    float t1c = (p <= 1) ? K3 : (p == 2 ? -K3 : -K23);
    float t2c = (p == 0) ? K3 : (p == 3 ? K23 : -K3);
    float t3c = (p == 0) ? K6 : (p == 2 ? K3 : -K3);

    stage(hbase, smem0);

    for (int s = 0; s < NS; s++) {
        int h0 = hbase + s * SS;

        CP_WAIT0();                 // this thread's copies for strip s done
        __syncthreads();            // everyone's copies visible

        if (s + 1 < NS)             // overlap next strip's loads with consume
            stage(h0 + SS, ((s + 1) & 1) ? smem1 : smem0);

        const float* buf = tile[s & 1];
        float ring[4][4];
        float* outbase = out + ((size_t)(b * HH + h0) * WW + (w0 + wl)) * 128
                             + (c * 16 + p * 4);

        #pragma unroll
        for (int t = 0; t < NT; t++) {
            const float4* tp = (const float4*)&buf[t * TSTRIDE + c * TPAD + wl];
            float4 A = tp[0];
            float4 B = tp[1];

            int r = h0 - 1 + t;
            bool rv = (r >= 0) && (r < HH);

            float h0v = fmaf(t0c, A.x, fmaf(t1c, A.y, fmaf(t2c, A.z, t3c * A.w)));
            float h1v = fmaf(t0c, A.y, fmaf(t1c, A.z, fmaf(t2c, A.w, t3c * B.x)));
            float h2v = fmaf(t0c, A.z, fmaf(t1c, A.w, fmaf(t2c, B.x, t3c * B.y)));
            float h3v = fmaf(t0c, A.w, fmaf(t1c, B.x, fmaf(t2c, B.y, t3c * B.z)));
            if (!rv) { h0v = 0.0f; h1v = 0.0f; h2v = 0.0f; h3v = 0.0f; }

            ring[0][t & 3] = h0v;
            ring[1][t & 3] = h1v;
            ring[2][t & 3] = h2v;
            ring[3][t & 3] = h3v;

            if (t >= 3) {
                float* orow = outbase + (size_t)(t - 3) * (WW * 128);
                #pragma unroll
                for (int q = 0; q < 4; q++) {
                    float4 o;
                    cheb4(ring[q][(t - 3) & 3], ring[q][(t - 2) & 3],
                          ring[q][(t - 1) & 3], ring[q][t & 3],
                          o.x, o.y, o.z, o.w);
                    __stcs((float4*)(orow + q * 128), o);
                }
            }
        }

        __syncthreads();            // readers done before buffer is re-staged
    }
}

extern "C" void kernel_launch(void* const* d_in, const int* in_sizes, int n_in,
                              void* d_out, int out_size) {
    const float* x = (const float*)d_in[0];
    float* out = (float*)d_out;
    // 8 b * 8 hg * 8 wt = 512 blocks of 256 threads
    cheb_kernel<<<512, 256>>>(x, out);
}

// round 16
// speedup vs baseline: 1.0904x; 1.0904x over previous
#include <cuda_runtime.h>
#include <cstddef>

// ChebychevTransform: x[8,256,256,8] f32 -> out[8,256,256,128] f32
// out[b,h,w, c*16 + p*4 + k] = sum_{i,j} T[p,j]*T[k,i]*x[b,h+i-1,w+j-1,c]
// (zero pad: 1 before / 2 after, TF SAME n=4)
// T = [[1/6,1/3,1/3,1/6],[1/3,1/3,-1/3,-1/3],[1/3,-1/3,-1/3,1/3],[1/3,-2/3,2/3,-1/3]]
//
// Warp = one (b, w, 8-row strip). lane = (j=lane>>3, c=lane&7).
// Loads:  one coalesced 128B LDG per row; interior strips use base+immediate
//         offsets (no clamp ALU). Horiz: 2-stage shfl butterfly (xor24, xor8).
// Vert:   per-lane over the 11-row register window; edge strips zero padding
//         rows (hs==0: row -1; hs==31: rows 256 AND 257).
// Stores: lane writes float4 at (c*16 + bitrev2(j)*4) -> 4 dense STG.128.CS/px
//         (evict-first: the 256MB write-once stream must not thrash L2).
// Block = 128 threads for finer wave packing (only change vs R10).

#define HH 256
#define WW 256
#define CC 8
#define SS 8
#define NR (SS + 3)
#define ROWF (WW * CC)   // floats per image row

__device__ __forceinline__ void cheb4(float x0, float x1, float x2, float x3,
                                      float& y0, float& y1, float& y2, float& y3) {
    const float K3 = 1.0f / 3.0f;
    const float K6 = 1.0f / 6.0f;
    float s0 = x0 + x3, s1 = x1 + x2;
    float d0 = x0 - x3, d1 = x1 - x2;
    y0 = fmaf(s1, K3, s0 * K6);
    y1 = (d0 + d1) * K3;
    y2 = (s0 - s1) * K3;
    y3 = fmaf(d1, -2.0f, d0) * K3;
}

__global__ __launch_bounds__(128)
void cheb_kernel(const float* __restrict__ x, float* __restrict__ out) {
    const unsigned FULL = 0xffffffffu;
    int tid  = blockIdx.x * 128 + threadIdx.x;
    int lane = tid & 31;
    int wid  = tid >> 5;                 // 65536 warps
    int w    = wid & (WW - 1);
    int hs   = (wid >> 8) & 31;          // 32 strips of 8 rows
    int b    = wid >> 13;
    int h0   = hs * SS;

    int j  = lane >> 3;                  // horizontal tap 0..3
    int cl = lane & 7;                   // channel 0..7

    // lane's load column (clamped) + validity at w edges
    int wj  = w - 1 + j;
    bool wv = (wj >= 0) && (wj < WW);
    int cw  = min(max(wj, 0), WW - 1);
    const float* lbase = x + ((size_t)b * HH * WW + cw) * CC + cl;

    // ---- load phase: 11 coalesced 128B LDGs ----
    float raw[NR];
    if (hs != 0 && hs != 31) {
        const float* rp = lbase + (size_t)(h0 - 1) * ROWF;
        #pragma unroll
        for (int t = 0; t < NR; t++)
            raw[t] = rp[t * ROWF];
    } else {
        #pragma unroll
        for (int t = 0; t < NR; t++) {
            int rc = min(max(h0 - 1 + t, 0), HH - 1);
            raw[t] = lbase[(size_t)rc * ROWF];
        }
    }
    if (!wv) {
        #pragma unroll
        for (int t = 0; t < NR; t++) raw[t] = 0.0f;
    }

    // ---- horizontal butterfly via shuffles ----
    const float K3 = 1.0f / 3.0f, K6 = 1.0f / 6.0f, K23 = 2.0f / 3.0f;
    float ca = (j == 0) ? K6 : -K3;
    float cb = (j == 3) ? K23 : ((j == 2) ? -K3 : K3);

    float u[NR];
    #pragma unroll
    for (int t = 0; t < NR; t++) {
        float s  = __shfl_xor_sync(FULL, raw[t], 24);
        float av = (j < 2) ? (raw[t] + s) : (raw[t] - s);
        float bv = __shfl_xor_sync(FULL, av, 8);
        u[t] = fmaf(ca, av, cb * bv);
    }
    if (hs == 0)  u[0] = 0.0f;                              // row -1
    if (hs == 31) { u[NR - 2] = 0.0f; u[NR - 1] = 0.0f; }   // rows 256, 257

    // ---- vertical butterflies + dense streaming stores ----
    int p = ((j & 1) << 1) | (j >> 1);               // bitrev2
    float* outp = out + ((size_t)(b * HH + h0) * WW + w) * (CC * 16)
                      + (cl * 16 + p * 4);
    #pragma unroll
    for (int s = 0; s < SS; s++) {
        float4 o;
        cheb4(u[s], u[s + 1], u[s + 2], u[s + 3], o.x, o.y, o.z, o.w);
        __stcs((float4*)(outp + (size_t)s * (ROWF * 16)), o);
    }
}

extern "C" void kernel_launch(void* const* d_in, const int* in_sizes, int n_in,
                              void* d_out, int out_size) {
    const float* x = (const float*)d_in[0];
    float* out = (float*)d_out;
    // 65536 warps -> 16384 blocks of 128 threads
    cheb_kernel<<<16384, 128>>>(x, out);
}